// round 1
// baseline (speedup 1.0000x reference)
#include <cuda_runtime.h>

#define S 4096
#define DM 1024
#define H 16
#define HD 64
#define WIN 512

// Scratch (allowed: static __device__ arrays, no allocation)
__device__ float g_k[H * S * HD];
__device__ float g_q[H * S * HD];
__device__ float g_v[H * S * HD];

// ---------------------------------------------------------------------------
// KQV GEMM: C[4096,3072] = x[4096,1024] @ w[1024,3072], scattered head-major
// 128x128 block tile, BK=16, 8x8 per thread (split 4+4), 256 threads.
// ---------------------------------------------------------------------------
__global__ __launch_bounds__(256) void kqv_gemm(const float* __restrict__ x,
                                                const float* __restrict__ w) {
    __shared__ float As[16 * 128];   // transposed: As[k][m]
    __shared__ float Bs[16 * 128];   // Bs[k][n]

    const int tid  = threadIdx.x;
    const int brow = blockIdx.y;     // 0..31
    const int bcol = blockIdx.x;     // 0..23
    const int trow = tid >> 4;       // 0..15
    const int tcol = tid & 15;       // 0..15

    float acc[8][8];
#pragma unroll
    for (int i = 0; i < 8; i++)
#pragma unroll
        for (int j = 0; j < 8; j++) acc[i][j] = 0.f;

    for (int kt = 0; kt < 64; ++kt) {
        // A tile: 128 rows x 16 k, transposed store
#pragma unroll
        for (int i = 0; i < 2; i++) {
            int f    = tid + i * 256;      // 0..511 float4s
            int arow = f >> 2;             // 0..127
            int kc4  = f & 3;              // 0..3
            float4 v = *(const float4*)&x[(brow * 128 + arow) * DM + kt * 16 + kc4 * 4];
            As[(kc4 * 4 + 0) * 128 + arow] = v.x;
            As[(kc4 * 4 + 1) * 128 + arow] = v.y;
            As[(kc4 * 4 + 2) * 128 + arow] = v.z;
            As[(kc4 * 4 + 3) * 128 + arow] = v.w;
        }
        // B tile: 16 k x 128 cols
#pragma unroll
        for (int i = 0; i < 2; i++) {
            int f   = tid + i * 256;
            int bk  = f >> 5;              // 0..15
            int bc4 = f & 31;              // 0..31
            *(float4*)&Bs[bk * 128 + bc4 * 4] =
                *(const float4*)&w[(kt * 16 + bk) * 3072 + bcol * 128 + bc4 * 4];
        }
        __syncthreads();
#pragma unroll
        for (int k = 0; k < 16; ++k) {
            float a[8], b[8];
            *(float4*)&a[0] = *(const float4*)&As[k * 128 + trow * 4];
            *(float4*)&a[4] = *(const float4*)&As[k * 128 + 64 + trow * 4];
            *(float4*)&b[0] = *(const float4*)&Bs[k * 128 + tcol * 4];
            *(float4*)&b[4] = *(const float4*)&Bs[k * 128 + 64 + tcol * 4];
#pragma unroll
            for (int i = 0; i < 8; i++)
#pragma unroll
                for (int j = 0; j < 8; j++)
                    acc[i][j] = fmaf(a[i], b[j], acc[i][j]);
        }
        __syncthreads();
    }

    // Epilogue: scatter to g_k / g_q / g_v, layout [h][s][d]
#pragma unroll
    for (int rh = 0; rh < 2; rh++) {
#pragma unroll
        for (int r = 0; r < 4; r++) {
            int row = brow * 128 + rh * 64 + trow * 4 + r;
#pragma unroll
            for (int ch = 0; ch < 2; ch++) {
                int col   = bcol * 128 + ch * 64 + tcol * 4;  // aligned 4, same head
                int chunk = col >> 10;                        // 0:k 1:q 2:v
                int cc    = col & 1023;
                int h     = cc >> 6;
                int d     = cc & 63;
                float* dst = (chunk == 0) ? g_k : (chunk == 1) ? g_q : g_v;
                float4 v;
                v.x = acc[rh * 4 + r][ch * 4 + 0];
                v.y = acc[rh * 4 + r][ch * 4 + 1];
                v.z = acc[rh * 4 + r][ch * 4 + 2];
                v.w = acc[rh * 4 + r][ch * 4 + 3];
                *(float4*)&dst[(h * S + row) * HD + d] = v;
            }
        }
    }
}

// ---------------------------------------------------------------------------
// Flash attention with ALiBi + sliding window. Block = (head, 64-query tile).
// 256 threads as 16x16, 4x4 micro-tile each. fp32.
// ---------------------------------------------------------------------------
__global__ __launch_bounds__(256) void attn_kernel(float* __restrict__ out) {
    __shared__ float Qs[64 * 64];   // Qs[row][d], natural
    __shared__ float KP[64 * 64];   // union: Kt swizzled [d][n'] / P [row][key]
    __shared__ float Vs[64 * 64];   // Vs[key][d], natural

    const int tid = threadIdx.x;
    const int tx  = tid & 15;       // key / out-dim group
    const int ty  = tid >> 4;       // query row group
    const int qt  = blockIdx.x;     // 0..63
    const int h   = blockIdx.y;     // 0..15
    const int q0  = qt * 64;

    const float slope = exp2f(-0.5f * (float)(h + 1));  // 1/(2^8)^((h+1)/16)
    const float* __restrict__ qp = g_q + h * S * HD;
    const float* __restrict__ kp = g_k + h * S * HD;
    const float* __restrict__ vp = g_v + h * S * HD;

    // Load Q tile (coalesced)
#pragma unroll
    for (int i = 0; i < 4; i++) {
        int f   = tid + i * 256;    // 0..1023 float4s
        int row = f >> 4;
        int d4  = f & 15;
        *(float4*)&Qs[row * 64 + d4 * 4] = *(const float4*)&qp[(q0 + row) * HD + d4 * 4];
    }

    float o[4][4];
    float m[4], l[4];
#pragma unroll
    for (int r = 0; r < 4; r++) {
        m[r] = -1e30f;
        l[r] = 0.f;
#pragma unroll
        for (int c = 0; c < 4; c++) o[r][c] = 0.f;
    }

    const int kt0 = (qt >= 8) ? (qt - 8) : 0;
    for (int kt = kt0; kt <= qt; ++kt) {
        const int kb = kt * 64;
        __syncthreads();  // KP/Vs free from previous iteration
        // Load K (transposed + XOR swizzle) and V (natural)
#pragma unroll
        for (int i = 0; i < 4; i++) {
            int f  = tid + i * 256;
            int n  = f >> 4;         // key 0..63
            int d4 = f & 15;         // dim group
            float4 kv = *(const float4*)&kp[(kb + n) * HD + d4 * 4];
            int nb = (((n >> 2) ^ d4) << 2) + (n & 3);  // swizzled n
            KP[(d4 * 4 + 0) * 64 + nb] = kv.x;
            KP[(d4 * 4 + 1) * 64 + nb] = kv.y;
            KP[(d4 * 4 + 2) * 64 + nb] = kv.z;
            KP[(d4 * 4 + 3) * 64 + nb] = kv.w;
            *(float4*)&Vs[n * 64 + d4 * 4] = *(const float4*)&vp[(kb + n) * HD + d4 * 4];
        }
        __syncthreads();

        // S = Q K^T (4x4 per thread)
        float s[4][4];
#pragma unroll
        for (int r = 0; r < 4; r++)
#pragma unroll
            for (int c = 0; c < 4; c++) s[r][c] = 0.f;

#pragma unroll 8
        for (int d = 0; d < 64; ++d) {
            float4 kf = *(const float4*)&KP[d * 64 + ((tx ^ (d >> 2)) << 2)];
#pragma unroll
            for (int r = 0; r < 4; r++) {
                float qv = Qs[(ty * 4 + r) * 64 + d];
                s[r][0] = fmaf(qv, kf.x, s[r][0]);
                s[r][1] = fmaf(qv, kf.y, s[r][1]);
                s[r][2] = fmaf(qv, kf.z, s[r][2]);
                s[r][3] = fmaf(qv, kf.w, s[r][3]);
            }
        }

        // Bias + mask + online softmax
#pragma unroll
        for (int r = 0; r < 4; ++r) {
            int i = q0 + ty * 4 + r;
            float mx = -1e30f;
#pragma unroll
            for (int c = 0; c < 4; ++c) {
                int j    = kb + tx * 4 + c;
                int dist = i - j;
                float v = (dist >= 0 && dist <= WIN)
                              ? s[r][c] * 0.03125f + slope * (float)(j - i)
                              : -1e30f;
                s[r][c] = v;
                mx = fmaxf(mx, v);
            }
#pragma unroll
            for (int off = 8; off >= 1; off >>= 1)
                mx = fmaxf(mx, __shfl_xor_sync(0xffffffffu, mx, off));
            float mn    = fmaxf(m[r], mx);
            float alpha = __expf(m[r] - mn);
            m[r] = mn;
            float rs = 0.f;
#pragma unroll
            for (int c = 0; c < 4; ++c) {
                float p = __expf(s[r][c] - mn);  // masked: exp(-1e30 - finite) -> 0
                s[r][c] = p;
                rs += p;
            }
#pragma unroll
            for (int off = 8; off >= 1; off >>= 1)
                rs += __shfl_xor_sync(0xffffffffu, rs, off);
            l[r] = l[r] * alpha + rs;
#pragma unroll
            for (int c = 0; c < 4; ++c) o[r][c] *= alpha;
        }

        __syncthreads();  // done reading KP as K
        // Write P into KP as P[row][key]
#pragma unroll
        for (int r = 0; r < 4; ++r) {
            float4 pv;
            pv.x = s[r][0]; pv.y = s[r][1]; pv.z = s[r][2]; pv.w = s[r][3];
            *(float4*)&KP[(ty * 4 + r) * 64 + tx * 4] = pv;
        }
        __syncthreads();

        // O += P V (thread owns rows ty*4.., dims tx*4..)
#pragma unroll 8
        for (int kk = 0; kk < 64; ++kk) {
            float4 vv = *(const float4*)&Vs[kk * 64 + tx * 4];
#pragma unroll
            for (int r = 0; r < 4; ++r) {
                float p = KP[(ty * 4 + r) * 64 + kk];  // broadcast
                o[r][0] = fmaf(p, vv.x, o[r][0]);
                o[r][1] = fmaf(p, vv.y, o[r][1]);
                o[r][2] = fmaf(p, vv.z, o[r][2]);
                o[r][3] = fmaf(p, vv.w, o[r][3]);
            }
        }
    }

    // Normalize and write out [s][h*64+d]
#pragma unroll
    for (int r = 0; r < 4; ++r) {
        float inv = 1.f / l[r];
        int i = q0 + ty * 4 + r;
        float4 res;
        res.x = o[r][0] * inv;
        res.y = o[r][1] * inv;
        res.z = o[r][2] * inv;
        res.w = o[r][3] * inv;
        *(float4*)&out[i * DM + h * HD + tx * 4] = res;
    }
}

// ---------------------------------------------------------------------------
extern "C" void kernel_launch(void* const* d_in, const int* in_sizes, int n_in,
                              void* d_out, int out_size) {
    const float* x = (const float*)d_in[0];
    const float* w = (const float*)d_in[1];
    // Robust to input-order surprises: x has 4096*1024 elems, w has 1024*3072.
    if (n_in >= 2 && in_sizes[0] == 1024 * 3072 && in_sizes[1] == S * DM) {
        const float* t = x; x = w; w = t;
    }
    float* out = (float*)d_out;

    dim3 ggrid(24, 32);          // 3072/128 x 4096/128
    kqv_gemm<<<ggrid, 256>>>(x, w);

    dim3 agrid(S / 64, H);       // 64 query tiles x 16 heads
    attn_kernel<<<agrid, 256>>>(out);
}

// round 3
// speedup vs baseline: 1.7878x; 1.7878x over previous
#include <cuda_runtime.h>
#include <cstdint>

#define S 4096
#define DM 1024
#define H 16
#define HD 64
#define WIN 512
#define NK 3072

// ---------------- device scratch (no allocation allowed) -------------------
__device__ float g_k[H * S * HD];
__device__ float g_q[H * S * HD];
__device__ float g_v[H * S * HD];
__device__ float g_xc[S * DM];        // x rounded to tf32
__device__ float g_wc[DM * NK];       // w rounded to tf32 (same [k][n] layout)

// ---------------- helpers ---------------------------------------------------
__device__ __forceinline__ float tf32_rna(float x) {
    float r;
    asm("cvt.rna.tf32.f32 %0, %1;" : "=f"(r) : "f"(x));
    return r;
}
__device__ __forceinline__ uint32_t smem_u32(const void* p) {
    uint32_t a;
    asm("{ .reg .u64 t; cvta.to.shared.u64 t, %1; cvt.u32.u64 %0, t; }"
        : "=r"(a) : "l"(p));
    return a;
}
__device__ __forceinline__ void cp16(uint32_t dst, const void* src) {
    asm volatile("cp.async.cg.shared.global [%0], [%1], 16;" :: "r"(dst), "l"(src));
}
__device__ __forceinline__ void cp_commit() {
    asm volatile("cp.async.commit_group;" ::: "memory");
}
__device__ __forceinline__ void cp_wait2() {
    asm volatile("cp.async.wait_group 2;" ::: "memory");
}
// D += A*B : m16n8k8 tf32
__device__ __forceinline__ void mma1688(float* c, const uint32_t* a, const uint32_t* b) {
    asm volatile(
        "mma.sync.aligned.m16n8k8.row.col.f32.tf32.tf32.f32 "
        "{%0,%1,%2,%3}, {%4,%5,%6,%7}, {%8,%9}, {%0,%1,%2,%3};"
        : "+f"(c[0]), "+f"(c[1]), "+f"(c[2]), "+f"(c[3])
        : "r"(a[0]), "r"(a[1]), "r"(a[2]), "r"(a[3]), "r"(b[0]), "r"(b[1]));
}

// ---------------- prep: round inputs to tf32 --------------------------------
__global__ __launch_bounds__(256) void prep_x(const float* __restrict__ x) {
    int i = blockIdx.x * blockDim.x + threadIdx.x;   // 1M float4s
    float4 v = ((const float4*)x)[i];
    v.x = tf32_rna(v.x); v.y = tf32_rna(v.y); v.z = tf32_rna(v.z); v.w = tf32_rna(v.w);
    ((float4*)g_xc)[i] = v;
}
__global__ __launch_bounds__(256) void prep_w(const float* __restrict__ w) {
    int i = blockIdx.x * blockDim.x + threadIdx.x;   // 768K float4s
    float4 v = ((const float4*)w)[i];
    v.x = tf32_rna(v.x); v.y = tf32_rna(v.y); v.z = tf32_rna(v.z); v.w = tf32_rna(v.w);
    ((float4*)g_wc)[i] = v;
}

// ---------------- tf32 mma.sync KQV GEMM ------------------------------------
// C[4096,3072] = xc[4096,1024] @ wc[1024,3072]; block 128x128, BK=16, 4 stages.
#define BK 16
#define ASTRIDE 20            // floats per A smem row (16 + pad, conflict-free gather)
#define BSTRIDE 136           // floats per B smem row (128 + pad)
#define A_BYTES (128 * ASTRIDE * 4)        // 10240
#define B_BYTES (BK * BSTRIDE * 4)         // 8704
#define STAGE_BYTES (A_BYTES + B_BYTES)    // 18944
#define NSTAGES 4
#define GEMM_SMEM (NSTAGES * STAGE_BYTES)  // 75776

__device__ __forceinline__ void load_stage(uint32_t sb, int st, int kt, int tid,
                                           const float* __restrict__ xA,
                                           const float* __restrict__ wB) {
    uint32_t ab = sb + st * STAGE_BYTES;
    uint32_t bb = ab + A_BYTES;
#pragma unroll
    for (int u = 0; u < 2; u++) {                      // A: 512 16B segs
        int i = tid + u * 256;
        int row = i >> 2, seg = i & 3;
        cp16(ab + row * (ASTRIDE * 4) + seg * 16,
             xA + (size_t)row * DM + kt * BK + seg * 4);
    }
#pragma unroll
    for (int u = 0; u < 2; u++) {                      // B: 512 16B segs
        int i = tid + u * 256;
        int row = i >> 5, seg = i & 31;
        cp16(bb + row * (BSTRIDE * 4) + seg * 16,
             wB + (size_t)(kt * BK + row) * NK + seg * 4);
    }
}

__global__ __launch_bounds__(256) void kqv_gemm_mma() {
    extern __shared__ __align__(16) uint8_t smem_raw[];
    uint32_t sb = smem_u32(smem_raw);
    const int tid  = threadIdx.x;
    const int warp = tid >> 5, lane = tid & 31;
    const int wm = warp >> 1;          // 0..3  (m offset wm*32)
    const int wn = warp & 1;           // 0..1  (n offset wn*64)
    const int m0 = blockIdx.y * 128;
    const int n0 = blockIdx.x * 128;

    const float* xA = g_xc + (size_t)m0 * DM;
    const float* wB = g_wc + n0;

    float c[2][8][4];
#pragma unroll
    for (int i = 0; i < 2; i++)
#pragma unroll
        for (int j = 0; j < 8; j++)
#pragma unroll
            for (int t = 0; t < 4; t++) c[i][j][t] = 0.f;

    // prologue: stages 0..2
#pragma unroll
    for (int s = 0; s < NSTAGES - 1; s++) {
        load_stage(sb, s, s, tid, xA, wB);
        cp_commit();
    }
    cp_wait2();
    __syncthreads();

    const int lr = lane >> 2;          // 0..7
    const int lc = lane & 3;           // 0..3

    for (int kt = 0; kt < DM / BK; kt++) {
        int st = kt & (NSTAGES - 1);
        const float* As = (const float*)(smem_raw + st * STAGE_BYTES);
        const float* Bs = (const float*)(smem_raw + st * STAGE_BYTES + A_BYTES);
#pragma unroll
        for (int kk = 0; kk < BK; kk += 8) {
            uint32_t a[2][4], b[8][2];
#pragma unroll
            for (int i = 0; i < 2; i++) {
                const uint32_t* ap =
                    (const uint32_t*)&As[(wm * 32 + i * 16 + lr) * ASTRIDE + kk + lc];
                a[i][0] = ap[0];
                a[i][1] = ap[8 * ASTRIDE];
                a[i][2] = ap[4];
                a[i][3] = ap[8 * ASTRIDE + 4];
            }
#pragma unroll
            for (int j = 0; j < 8; j++) {
                const uint32_t* bp =
                    (const uint32_t*)&Bs[(kk + lc) * BSTRIDE + wn * 64 + j * 8 + lr];
                b[j][0] = bp[0];
                b[j][1] = bp[4 * BSTRIDE];
            }
#pragma unroll
            for (int i = 0; i < 2; i++)
#pragma unroll
                for (int j = 0; j < 8; j++) mma1688(c[i][j], a[i], b[j]);
        }
        __syncthreads();
        int nk = kt + NSTAGES - 1;
        if (nk < DM / BK) load_stage(sb, nk & (NSTAGES - 1), nk, tid, xA, wB);
        cp_commit();
        cp_wait2();
        __syncthreads();
    }

    // epilogue: scatter to g_k/g_q/g_v. Warp's 64-col half is within one head.
    int gcol = n0 + wn * 64;
    int chunk = gcol >> 10;            // 0:k 1:q 2:v
    int cc = gcol & 1023;
    int h = cc >> 6;
    float* dst = (chunk == 0) ? g_k : (chunk == 1) ? g_q : g_v;
    float* base = dst + ((size_t)h * S + m0 + wm * 32) * HD;
#pragma unroll
    for (int i = 0; i < 2; i++) {
        int r0 = i * 16 + lr;
#pragma unroll
        for (int j = 0; j < 8; j++) {
            int d = j * 8 + 2 * lc;
            float2 v01 = make_float2(c[i][j][0], c[i][j][1]);
            float2 v23 = make_float2(c[i][j][2], c[i][j][3]);
            *(float2*)&base[(size_t)r0 * HD + d] = v01;
            *(float2*)&base[(size_t)(r0 + 8) * HD + d] = v23;
        }
    }
}

// ---------------------------------------------------------------------------
// Flash attention with ALiBi + sliding window (unchanged, fp32).
// ---------------------------------------------------------------------------
__global__ __launch_bounds__(256) void attn_kernel(float* __restrict__ out) {
    __shared__ float Qs[64 * 64];
    __shared__ float KP[64 * 64];
    __shared__ float Vs[64 * 64];

    const int tid = threadIdx.x;
    const int tx = tid & 15;
    const int ty = tid >> 4;
    const int qt = blockIdx.x;
    const int h = blockIdx.y;
    const int q0 = qt * 64;

    const float slope = exp2f(-0.5f * (float)(h + 1));
    const float* __restrict__ qp = g_q + h * S * HD;
    const float* __restrict__ kp = g_k + h * S * HD;
    const float* __restrict__ vp = g_v + h * S * HD;

#pragma unroll
    for (int i = 0; i < 4; i++) {
        int f = tid + i * 256;
        int row = f >> 4;
        int d4 = f & 15;
        *(float4*)&Qs[row * 64 + d4 * 4] = *(const float4*)&qp[(q0 + row) * HD + d4 * 4];
    }

    float o[4][4];
    float m[4], l[4];
#pragma unroll
    for (int r = 0; r < 4; r++) {
        m[r] = -1e30f;
        l[r] = 0.f;
#pragma unroll
        for (int c = 0; c < 4; c++) o[r][c] = 0.f;
    }

    const int kt0 = (qt >= 8) ? (qt - 8) : 0;
    for (int kt = kt0; kt <= qt; ++kt) {
        const int kb = kt * 64;
        __syncthreads();
#pragma unroll
        for (int i = 0; i < 4; i++) {
            int f = tid + i * 256;
            int n = f >> 4;
            int d4 = f & 15;
            float4 kv = *(const float4*)&kp[(kb + n) * HD + d4 * 4];
            int nb = (((n >> 2) ^ d4) << 2) + (n & 3);
            KP[(d4 * 4 + 0) * 64 + nb] = kv.x;
            KP[(d4 * 4 + 1) * 64 + nb] = kv.y;
            KP[(d4 * 4 + 2) * 64 + nb] = kv.z;
            KP[(d4 * 4 + 3) * 64 + nb] = kv.w;
            *(float4*)&Vs[n * 64 + d4 * 4] = *(const float4*)&vp[(kb + n) * HD + d4 * 4];
        }
        __syncthreads();

        float s[4][4];
#pragma unroll
        for (int r = 0; r < 4; r++)
#pragma unroll
            for (int c = 0; c < 4; c++) s[r][c] = 0.f;

#pragma unroll 8
        for (int d = 0; d < 64; ++d) {
            float4 kf = *(const float4*)&KP[d * 64 + ((tx ^ (d >> 2)) << 2)];
#pragma unroll
            for (int r = 0; r < 4; r++) {
                float qv = Qs[(ty * 4 + r) * 64 + d];
                s[r][0] = fmaf(qv, kf.x, s[r][0]);
                s[r][1] = fmaf(qv, kf.y, s[r][1]);
                s[r][2] = fmaf(qv, kf.z, s[r][2]);
                s[r][3] = fmaf(qv, kf.w, s[r][3]);
            }
        }

#pragma unroll
        for (int r = 0; r < 4; ++r) {
            int i = q0 + ty * 4 + r;
            float mx = -1e30f;
#pragma unroll
            for (int c = 0; c < 4; ++c) {
                int j = kb + tx * 4 + c;
                int dist = i - j;
                float v = (dist >= 0 && dist <= WIN)
                              ? s[r][c] * 0.03125f + slope * (float)(j - i)
                              : -1e30f;
                s[r][c] = v;
                mx = fmaxf(mx, v);
            }
#pragma unroll
            for (int off = 8; off >= 1; off >>= 1)
                mx = fmaxf(mx, __shfl_xor_sync(0xffffffffu, mx, off));
            float mn = fmaxf(m[r], mx);
            float alpha = __expf(m[r] - mn);
            m[r] = mn;
            float rs = 0.f;
#pragma unroll
            for (int c = 0; c < 4; ++c) {
                float p = __expf(s[r][c] - mn);
                s[r][c] = p;
                rs += p;
            }
#pragma unroll
            for (int off = 8; off >= 1; off >>= 1)
                rs += __shfl_xor_sync(0xffffffffu, rs, off);
            l[r] = l[r] * alpha + rs;
#pragma unroll
            for (int c = 0; c < 4; ++c) o[r][c] *= alpha;
        }

        __syncthreads();
#pragma unroll
        for (int r = 0; r < 4; ++r) {
            float4 pv;
            pv.x = s[r][0]; pv.y = s[r][1]; pv.z = s[r][2]; pv.w = s[r][3];
            *(float4*)&KP[(ty * 4 + r) * 64 + tx * 4] = pv;
        }
        __syncthreads();

#pragma unroll 8
        for (int kk = 0; kk < 64; ++kk) {
            float4 vv = *(const float4*)&Vs[kk * 64 + tx * 4];
#pragma unroll
            for (int r = 0; r < 4; ++r) {
                float p = KP[(ty * 4 + r) * 64 + kk];
                o[r][0] = fmaf(p, vv.x, o[r][0]);
                o[r][1] = fmaf(p, vv.y, o[r][1]);
                o[r][2] = fmaf(p, vv.z, o[r][2]);
                o[r][3] = fmaf(p, vv.w, o[r][3]);
            }
        }
    }

#pragma unroll
    for (int r = 0; r < 4; ++r) {
        float inv = 1.f / l[r];
        int i = q0 + ty * 4 + r;
        float4 res;
        res.x = o[r][0] * inv;
        res.y = o[r][1] * inv;
        res.z = o[r][2] * inv;
        res.w = o[r][3] * inv;
        *(float4*)&out[i * DM + h * HD + tx * 4] = res;
    }
}

// ---------------------------------------------------------------------------
extern "C" void kernel_launch(void* const* d_in, const int* in_sizes, int n_in,
                              void* d_out, int out_size) {
    const float* x = (const float*)d_in[0];
    const float* w = (const float*)d_in[1];
    if (n_in >= 2 && in_sizes[0] == DM * NK && in_sizes[1] == S * DM) {
        const float* t = x; x = w; w = t;
    }
    float* out = (float*)d_out;

    static int smem_set = 0;
    if (!smem_set) {
        cudaFuncSetAttribute(kqv_gemm_mma, cudaFuncAttributeMaxDynamicSharedMemorySize,
                             GEMM_SMEM);
        smem_set = 1;
    }

    prep_x<<<4096, 256>>>(x);            // 1M float4s
    prep_w<<<3072, 256>>>(w);            // 768K float4s

    dim3 ggrid(NK / 128, S / 128);       // 24 x 32
    kqv_gemm_mma<<<ggrid, 256, GEMM_SMEM>>>();

    dim3 agrid(S / 64, H);
    attn_kernel<<<agrid, 256>>>(out);
}

// round 5
// speedup vs baseline: 2.7460x; 1.5360x over previous
#include <cuda_runtime.h>
#include <cstdint>

#define S 4096
#define DM 1024
#define H 16
#define HD 64
#define WIN 512
#define NK 3072

// ---------------- device scratch (no allocation allowed) -------------------
__device__ float g_k[H * S * HD];
__device__ float g_q[H * S * HD];
__device__ float g_v[H * S * HD];
__device__ float g_xc[S * DM];        // x rounded to tf32
__device__ float g_wc[DM * NK];       // w rounded to tf32

// ---------------- helpers ---------------------------------------------------
__device__ __forceinline__ float tf32_rna(float x) {
    float r;
    asm("cvt.rna.tf32.f32 %0, %1;" : "=f"(r) : "f"(x));
    return r;
}
__device__ __forceinline__ uint32_t smem_u32(const void* p) {
    uint32_t a;
    asm("{ .reg .u64 t; cvta.to.shared.u64 t, %1; cvt.u32.u64 %0, t; }"
        : "=r"(a) : "l"(p));
    return a;
}
__device__ __forceinline__ void cp16(uint32_t dst, const void* src) {
    asm volatile("cp.async.cg.shared.global [%0], [%1], 16;" :: "r"(dst), "l"(src));
}
__device__ __forceinline__ void cp_commit() {
    asm volatile("cp.async.commit_group;" ::: "memory");
}
__device__ __forceinline__ void cp_wait0() {
    asm volatile("cp.async.wait_group 0;" ::: "memory");
}
__device__ __forceinline__ void cp_wait1() {
    asm volatile("cp.async.wait_group 1;" ::: "memory");
}
__device__ __forceinline__ void cp_wait2() {
    asm volatile("cp.async.wait_group 2;" ::: "memory");
}
// D += A*B : m16n8k8 tf32 (fragment maps verified by passing R3 GEMM)
__device__ __forceinline__ void mma1688(float* c, const uint32_t* a, const uint32_t* b) {
    asm volatile(
        "mma.sync.aligned.m16n8k8.row.col.f32.tf32.tf32.f32 "
        "{%0,%1,%2,%3}, {%4,%5,%6,%7}, {%8,%9}, {%0,%1,%2,%3};"
        : "+f"(c[0]), "+f"(c[1]), "+f"(c[2]), "+f"(c[3])
        : "r"(a[0]), "r"(a[1]), "r"(a[2]), "r"(a[3]), "r"(b[0]), "r"(b[1]));
}

// ---------------- prep: round inputs to tf32 --------------------------------
__global__ __launch_bounds__(256) void prep_x(const float* __restrict__ x) {
    int i = blockIdx.x * blockDim.x + threadIdx.x;
    float4 v = ((const float4*)x)[i];
    v.x = tf32_rna(v.x); v.y = tf32_rna(v.y); v.z = tf32_rna(v.z); v.w = tf32_rna(v.w);
    ((float4*)g_xc)[i] = v;
}
__global__ __launch_bounds__(256) void prep_w(const float* __restrict__ w) {
    int i = blockIdx.x * blockDim.x + threadIdx.x;
    float4 v = ((const float4*)w)[i];
    v.x = tf32_rna(v.x); v.y = tf32_rna(v.y); v.z = tf32_rna(v.z); v.w = tf32_rna(v.w);
    ((float4*)g_wc)[i] = v;
}

// ---------------- tf32 mma.sync KQV GEMM (as R3, epilogue rounds to tf32) ---
#define BK 16
#define ASTRIDE 20
#define BSTRIDE 136
#define A_BYTES (128 * ASTRIDE * 4)
#define B_BYTES (BK * BSTRIDE * 4)
#define STAGE_BYTES (A_BYTES + B_BYTES)
#define NSTAGES 4
#define GEMM_SMEM (NSTAGES * STAGE_BYTES)

__device__ __forceinline__ void load_stage(uint32_t sb, int st, int kt, int tid,
                                           const float* __restrict__ xA,
                                           const float* __restrict__ wB) {
    uint32_t ab = sb + st * STAGE_BYTES;
    uint32_t bb = ab + A_BYTES;
#pragma unroll
    for (int u = 0; u < 2; u++) {
        int i = tid + u * 256;
        int row = i >> 2, seg = i & 3;
        cp16(ab + row * (ASTRIDE * 4) + seg * 16,
             xA + (size_t)row * DM + kt * BK + seg * 4);
    }
#pragma unroll
    for (int u = 0; u < 2; u++) {
        int i = tid + u * 256;
        int row = i >> 5, seg = i & 31;
        cp16(bb + row * (BSTRIDE * 4) + seg * 16,
             wB + (size_t)(kt * BK + row) * NK + seg * 4);
    }
}

__global__ __launch_bounds__(256) void kqv_gemm_mma() {
    extern __shared__ __align__(16) uint8_t smem_raw[];
    uint32_t sb = smem_u32(smem_raw);
    const int tid  = threadIdx.x;
    const int warp = tid >> 5, lane = tid & 31;
    const int wm = warp >> 1;
    const int wn = warp & 1;
    const int m0 = blockIdx.y * 128;
    const int n0 = blockIdx.x * 128;

    const float* xA = g_xc + (size_t)m0 * DM;
    const float* wB = g_wc + n0;

    float c[2][8][4];
#pragma unroll
    for (int i = 0; i < 2; i++)
#pragma unroll
        for (int j = 0; j < 8; j++)
#pragma unroll
            for (int t = 0; t < 4; t++) c[i][j][t] = 0.f;

#pragma unroll
    for (int s = 0; s < NSTAGES - 1; s++) {
        load_stage(sb, s, s, tid, xA, wB);
        cp_commit();
    }
    cp_wait2();
    __syncthreads();

    const int lr = lane >> 2;
    const int lc = lane & 3;

    for (int kt = 0; kt < DM / BK; kt++) {
        int st = kt & (NSTAGES - 1);
        const float* As = (const float*)(smem_raw + st * STAGE_BYTES);
        const float* Bs = (const float*)(smem_raw + st * STAGE_BYTES + A_BYTES);
#pragma unroll
        for (int kk = 0; kk < BK; kk += 8) {
            uint32_t a[2][4], b[8][2];
#pragma unroll
            for (int i = 0; i < 2; i++) {
                const uint32_t* ap =
                    (const uint32_t*)&As[(wm * 32 + i * 16 + lr) * ASTRIDE + kk + lc];
                a[i][0] = ap[0];
                a[i][1] = ap[8 * ASTRIDE];
                a[i][2] = ap[4];
                a[i][3] = ap[8 * ASTRIDE + 4];
            }
#pragma unroll
            for (int j = 0; j < 8; j++) {
                const uint32_t* bp =
                    (const uint32_t*)&Bs[(kk + lc) * BSTRIDE + wn * 64 + j * 8 + lr];
                b[j][0] = bp[0];
                b[j][1] = bp[4 * BSTRIDE];
            }
#pragma unroll
            for (int i = 0; i < 2; i++)
#pragma unroll
                for (int j = 0; j < 8; j++) mma1688(c[i][j], a[i], b[j]);
        }
        __syncthreads();
        int nk = kt + NSTAGES - 1;
        if (nk < DM / BK) load_stage(sb, nk & (NSTAGES - 1), nk, tid, xA, wB);
        cp_commit();
        cp_wait2();
        __syncthreads();
    }

    int gcol = n0 + wn * 64;
    int chunk = gcol >> 10;
    int cc = gcol & 1023;
    int h = cc >> 6;
    float* dst = (chunk == 0) ? g_k : (chunk == 1) ? g_q : g_v;
    float* base = dst + ((size_t)h * S + m0 + wm * 32) * HD;
#pragma unroll
    for (int i = 0; i < 2; i++) {
        int r0 = i * 16 + lr;
#pragma unroll
        for (int j = 0; j < 8; j++) {
            int d = j * 8 + 2 * lc;
            float2 v01 = make_float2(tf32_rna(c[i][j][0]), tf32_rna(c[i][j][1]));
            float2 v23 = make_float2(tf32_rna(c[i][j][2]), tf32_rna(c[i][j][3]));
            *(float2*)&base[(size_t)r0 * HD + d] = v01;
            *(float2*)&base[(size_t)(r0 + 8) * HD + d] = v23;
        }
    }
}

// ---------------------------------------------------------------------------
// Tensor-core flash attention. Block = 128 queries x 1 head, 8 warps.
// Warp w owns rows w*16..w*16+15. Key tiles of 64, 10 per block (window 512).
// smem floats: QP[128*72] (Q then reused as per-warp P), K/V stages [2][2][64*72]
// ---------------------------------------------------------------------------
#define AST 72                      // smem row stride (floats): conflict-free
#define QP_F 0
#define KV_F(s) (9216 + (s) * 9216) // K at +0, V at +4608
#define ATTN_SMEM ((9216 + 2 * 9216) * 4)
#define SCL 0.03125f

__device__ __forceinline__ void load_kv(uint32_t sb, int s, int kt, int tid,
                                        const float* __restrict__ kp,
                                        const float* __restrict__ vp) {
    uint32_t kb = sb + KV_F(s) * 4;
    uint32_t vb = kb + 4608 * 4;
    const float* kg = kp + (size_t)(kt * 64) * HD;
    const float* vg = vp + (size_t)(kt * 64) * HD;
#pragma unroll
    for (int u = 0; u < 4; u++) {
        int i = tid + u * 256;
        int row = i >> 4, seg = i & 15;
        cp16(kb + row * (AST * 4) + seg * 16, kg + row * HD + seg * 4);
    }
#pragma unroll
    for (int u = 0; u < 4; u++) {
        int i = tid + u * 256;
        int row = i >> 4, seg = i & 15;
        cp16(vb + row * (AST * 4) + seg * 16, vg + row * HD + seg * 4);
    }
}

__global__ __launch_bounds__(256, 1) void attn_tc(float* __restrict__ out) {
    extern __shared__ __align__(16) uint8_t smem_raw[];
    float* sm = (float*)smem_raw;
    uint32_t sb = smem_u32(smem_raw);

    const int tid = threadIdx.x;
    const int w = tid >> 5, lane = tid & 31;
    const int lr = lane >> 2, lc = lane & 3;
    const int qt = blockIdx.x;          // 0..31 (128-query tiles)
    const int h = blockIdx.y;
    const int q0 = qt * 128;

    const float slope = exp2f(-0.5f * (float)(h + 1));
    const float* __restrict__ qp = g_q + (size_t)h * S * HD;
    const float* __restrict__ kp = g_k + (size_t)h * S * HD;
    const float* __restrict__ vp = g_v + (size_t)h * S * HD;

    const int kt0 = (qt >= 4) ? (2 * qt - 8) : 0;
    const int kt1 = 2 * qt + 1;

    // Q tile -> smem
#pragma unroll
    for (int u = 0; u < 8; u++) {
        int i = tid + u * 256;
        int row = i >> 4, seg = i & 15;
        cp16(sb + QP_F * 4 + row * (AST * 4) + seg * 16,
             qp + (size_t)(q0 + row) * HD + seg * 4);
    }
    cp_commit();
    load_kv(sb, 0, kt0, tid, kp, vp);
    cp_commit();
    cp_wait0();
    __syncthreads();

    // Q fragments (warp-private rows) -> registers
    uint32_t qa[8][4];
    {
        const float* Qs = sm + QP_F + (w * 16) * AST;
#pragma unroll
        for (int k8 = 0; k8 < 8; k8++) {
            const uint32_t* p = (const uint32_t*)&Qs[lr * AST + k8 * 8 + lc];
            qa[k8][0] = p[0];
            qa[k8][1] = p[8 * AST];
            qa[k8][2] = p[4];
            qa[k8][3] = p[8 * AST + 4];
        }
    }

    float o[8][4];
    float m0r = -1e30f, m1r = -1e30f, l0 = 0.f, l1 = 0.f;
#pragma unroll
    for (int nt = 0; nt < 8; nt++)
#pragma unroll
        for (int t = 0; t < 4; t++) o[nt][t] = 0.f;

    const int i0 = q0 + w * 16 + lr;
    const int i1 = i0 + 8;
    float* Pw = sm + QP_F + (w * 16) * AST;   // warp-private P region (= Q rows)

    for (int kt = kt0; kt <= kt1; kt++) {
        int st = (kt - kt0) & 1;
        if (kt < kt1) {
            load_kv(sb, st ^ 1, kt + 1, tid, kp, vp);
            cp_commit();
            cp_wait1();
        } else {
            cp_wait0();
        }
        __syncthreads();

        const float* Ks = sm + KV_F(st);
        const float* Vs = Ks + 4608;
        const int kb = kt * 64;

        // ---- S = Q K^T ----
        float sc[8][4];
#pragma unroll
        for (int nt = 0; nt < 8; nt++) {
#pragma unroll
            for (int t = 0; t < 4; t++) sc[nt][t] = 0.f;
#pragma unroll
            for (int k8 = 0; k8 < 8; k8++) {
                uint32_t b[2];
                const uint32_t* bp =
                    (const uint32_t*)&Ks[(nt * 8 + lr) * AST + k8 * 8 + lc];
                b[0] = bp[0];
                b[1] = bp[4];
                mma1688(sc[nt], qa[k8], b);
            }
        }

        // ---- masked ALiBi softmax on fragments ----
        float mx0 = -3e38f, mx1 = -3e38f;
#pragma unroll
        for (int nt = 0; nt < 8; nt++) {
            int j0 = kb + nt * 8 + 2 * lc;
            int d00 = i0 - j0;
            sc[nt][0] = (d00 >= 0 && d00 <= WIN)
                            ? fmaf(sc[nt][0], SCL, slope * (float)(-d00)) : -3e38f;
            mx0 = fmaxf(mx0, sc[nt][0]);
            int d01 = d00 - 1;
            sc[nt][1] = (d01 >= 0 && d01 <= WIN)
                            ? fmaf(sc[nt][1], SCL, slope * (float)(-d01)) : -3e38f;
            mx0 = fmaxf(mx0, sc[nt][1]);
            int d10 = i1 - j0;
            sc[nt][2] = (d10 >= 0 && d10 <= WIN)
                            ? fmaf(sc[nt][2], SCL, slope * (float)(-d10)) : -3e38f;
            mx1 = fmaxf(mx1, sc[nt][2]);
            int d11 = d10 - 1;
            sc[nt][3] = (d11 >= 0 && d11 <= WIN)
                            ? fmaf(sc[nt][3], SCL, slope * (float)(-d11)) : -3e38f;
            mx1 = fmaxf(mx1, sc[nt][3]);
        }
        mx0 = fmaxf(mx0, __shfl_xor_sync(0xffffffffu, mx0, 1));
        mx0 = fmaxf(mx0, __shfl_xor_sync(0xffffffffu, mx0, 2));
        mx1 = fmaxf(mx1, __shfl_xor_sync(0xffffffffu, mx1, 1));
        mx1 = fmaxf(mx1, __shfl_xor_sync(0xffffffffu, mx1, 2));

        float mn0 = fmaxf(m0r, mx0), mn1 = fmaxf(m1r, mx1);
        float al0 = __expf(m0r - mn0), al1 = __expf(m1r - mn1);
        m0r = mn0; m1r = mn1;

        float rs0 = 0.f, rs1 = 0.f;
#pragma unroll
        for (int nt = 0; nt < 8; nt++) {
            float p00 = tf32_rna(__expf(sc[nt][0] - mn0));
            float p01 = tf32_rna(__expf(sc[nt][1] - mn0));
            float p10 = tf32_rna(__expf(sc[nt][2] - mn1));
            float p11 = tf32_rna(__expf(sc[nt][3] - mn1));
            rs0 += p00 + p01;
            rs1 += p10 + p11;
            *(float2*)&Pw[lr * AST + nt * 8 + 2 * lc] = make_float2(p00, p01);
            *(float2*)&Pw[(lr + 8) * AST + nt * 8 + 2 * lc] = make_float2(p10, p11);
        }
        rs0 += __shfl_xor_sync(0xffffffffu, rs0, 1);
        rs0 += __shfl_xor_sync(0xffffffffu, rs0, 2);
        rs1 += __shfl_xor_sync(0xffffffffu, rs1, 1);
        rs1 += __shfl_xor_sync(0xffffffffu, rs1, 2);
        l0 = l0 * al0 + rs0;
        l1 = l1 * al1 + rs1;
#pragma unroll
        for (int nt = 0; nt < 8; nt++) {
            o[nt][0] *= al0; o[nt][1] *= al0;
            o[nt][2] *= al1; o[nt][3] *= al1;
        }
        __syncwarp();

        // ---- P fragments ----
        uint32_t pa[8][4];
#pragma unroll
        for (int k8 = 0; k8 < 8; k8++) {
            const uint32_t* p = (const uint32_t*)&Pw[lr * AST + k8 * 8 + lc];
            pa[k8][0] = p[0];
            pa[k8][1] = p[8 * AST];
            pa[k8][2] = p[4];
            pa[k8][3] = p[8 * AST + 4];
        }

        // ---- O += P V ----
#pragma unroll
        for (int nt = 0; nt < 8; nt++) {
#pragma unroll
            for (int k8 = 0; k8 < 8; k8++) {
                uint32_t b[2];
                const uint32_t* bp =
                    (const uint32_t*)&Vs[(k8 * 8 + lc) * AST + nt * 8 + lr];
                b[0] = bp[0];
                b[1] = bp[4 * AST];
                mma1688(o[nt], pa[k8], b);
            }
        }
        __syncthreads();
    }

    // ---- normalize + write ----
    float inv0 = 1.f / l0, inv1 = 1.f / l1;
    float* o0 = out + (size_t)i0 * DM + h * HD;
    float* o1 = out + (size_t)i1 * DM + h * HD;
#pragma unroll
    for (int nt = 0; nt < 8; nt++) {
        *(float2*)&o0[nt * 8 + 2 * lc] = make_float2(o[nt][0] * inv0, o[nt][1] * inv0);
        *(float2*)&o1[nt * 8 + 2 * lc] = make_float2(o[nt][2] * inv1, o[nt][3] * inv1);
    }
}

// ---------------------------------------------------------------------------
extern "C" void kernel_launch(void* const* d_in, const int* in_sizes, int n_in,
                              void* d_out, int out_size) {
    const float* x = (const float*)d_in[0];
    const float* w = (const float*)d_in[1];
    if (n_in >= 2 && in_sizes[0] == DM * NK && in_sizes[1] == S * DM) {
        const float* t = x; x = w; w = t;
    }
    float* out = (float*)d_out;

    static int attr_set = 0;
    if (!attr_set) {
        cudaFuncSetAttribute(kqv_gemm_mma, cudaFuncAttributeMaxDynamicSharedMemorySize,
                             GEMM_SMEM);
        cudaFuncSetAttribute(attn_tc, cudaFuncAttributeMaxDynamicSharedMemorySize,
                             ATTN_SMEM);
        attr_set = 1;
    }

    prep_x<<<4096, 256>>>(x);
    prep_w<<<3072, 256>>>(w);

    dim3 ggrid(NK / 128, S / 128);
    kqv_gemm_mma<<<ggrid, 256, GEMM_SMEM>>>();

    dim3 agrid(S / 128, H);
    attn_tc<<<agrid, 256, ATTN_SMEM>>>(out);
}

// round 7
// speedup vs baseline: 3.1667x; 1.1532x over previous
#include <cuda_runtime.h>
#include <cstdint>

#define S 4096
#define DM 1024
#define H 16
#define HD 64
#define WIN 512
#define NK 3072

// ---------------- device scratch (frag-major layouts) ----------------------
// g_xc : a-frag  [mt(256)][k8(128)][lane][4]
// g_wc : b-frag  [nt8(384)][k16(64)][lane][4]
// g_q2 : a-frag  [h][mt(256)][k8(8)][lane][4]        (k-dim = head dim d)
// g_k2 : b-frag  [h][nt8(512)][d16(4)][lane][4]      (k-dim = d, n = keys)
// g_v2 : b-frag  [h][t(64)][dt8(8)][k16(4)][lane][4] (k-dim = keys, n = d)
__device__ float g_xc[S * DM];
__device__ float g_wc[DM * NK];
__device__ float g_q2[H * S * HD];
__device__ float g_k2[H * S * HD];
__device__ float g_v2[H * S * HD];

// ---------------- helpers ---------------------------------------------------
__device__ __forceinline__ float tf32_rna(float x) {
    float r;
    asm("cvt.rna.tf32.f32 %0, %1;" : "=f"(r) : "f"(x));
    return r;
}
__device__ __forceinline__ uint32_t smem_u32(const void* p) {
    uint32_t a;
    asm("{ .reg .u64 t; cvta.to.shared.u64 t, %1; cvt.u32.u64 %0, t; }"
        : "=r"(a) : "l"(p));
    return a;
}
__device__ __forceinline__ void cp16(uint32_t dst, const void* src) {
    asm volatile("cp.async.cg.shared.global [%0], [%1], 16;" :: "r"(dst), "l"(src));
}
__device__ __forceinline__ void cp_commit() {
    asm volatile("cp.async.commit_group;" ::: "memory");
}
__device__ __forceinline__ void cp_wait0() { asm volatile("cp.async.wait_group 0;" ::: "memory"); }
__device__ __forceinline__ void cp_wait1() { asm volatile("cp.async.wait_group 1;" ::: "memory"); }
__device__ __forceinline__ void cp_wait2() { asm volatile("cp.async.wait_group 2;" ::: "memory"); }
__device__ __forceinline__ void mma1688(float* c, const uint32_t* a, const uint32_t* b) {
    asm volatile(
        "mma.sync.aligned.m16n8k8.row.col.f32.tf32.tf32.f32 "
        "{%0,%1,%2,%3}, {%4,%5,%6,%7}, {%8,%9}, {%0,%1,%2,%3};"
        : "+f"(c[0]), "+f"(c[1]), "+f"(c[2]), "+f"(c[3])
        : "r"(a[0]), "r"(a[1]), "r"(a[2]), "r"(a[3]), "r"(b[0]), "r"(b[1]));
}

// ---------------- prep: round to tf32 + frag-major scatter ------------------
// a-frag slot conventions (k8 block): s = 2*k4 + rowbit; lane = lr*4 + lc
// b-frag slot conventions (k16 block): s = k8b*2 + pair; lane = n8*4 + lc
__global__ __launch_bounds__(256) void prep_x(const float* __restrict__ x) {
    int row = blockIdx.x;            // 4096 blocks, one row each
    int k0 = threadIdx.x * 4;
    float4 v = *(const float4*)&x[(size_t)row * DM + k0];
    float vv[4] = {tf32_rna(v.x), tf32_rna(v.y), tf32_rna(v.z), tf32_rna(v.w)};
    int base = ((row >> 4) * 128 + (k0 >> 3)) * 128;
    int s = 2 * ((k0 >> 2) & 1) + ((row >> 3) & 1);
    int l0 = (row & 7) * 4;          // lanes l0..l0+3
#pragma unroll
    for (int t = 0; t < 4; t++) g_xc[base + (l0 + t) * 4 + s] = vv[t];
}
__global__ __launch_bounds__(256) void prep_w(const float* __restrict__ w) {
    int b = blockIdx.x;              // 3072 blocks; 3 per k row
    int k = b / 3;
    int n0 = (b % 3) * 1024 + threadIdx.x * 4;
    float4 v = *(const float4*)&w[(size_t)k * NK + n0];
    float vv[4] = {tf32_rna(v.x), tf32_rna(v.y), tf32_rna(v.z), tf32_rna(v.w)};
    int base = ((n0 >> 3) * 64 + (k >> 4)) * 128;
    int s = ((k >> 3) & 1) * 2 + ((k >> 2) & 1);
    int lc = k & 3;
#pragma unroll
    for (int t = 0; t < 4; t++) {
        int n = n0 + t;              // n0 4-aligned, same nt8 for all 4
        g_wc[base + ((n & 7) * 4 + lc) * 4 + s] = vv[t];
    }
}

// ---------------- tf32 mma.sync KQV GEMM, frag-major smem -------------------
// block 128x128, BK=16(one k16), 4 stages, stage = A 8KB + B 8KB.
#define GSTAGE_F 4096
#define GNSTAGES 4
#define GEMM_SMEM (GNSTAGES * GSTAGE_F * 4)

__device__ __forceinline__ void g_load_stage(uint32_t sb, int st, int kt16, int tid,
                                             int mt0, int n8b) {
    uint32_t ab = sb + st * (GSTAGE_F * 4);
    uint32_t bb = ab + 8192;
#pragma unroll
    for (int u = 0; u < 2; u++) {                  // A: 512 chunks
        int c = tid + u * 256;
        int mti = c >> 6, rem = c & 63;
        int k8l = rem >> 5, cb = rem & 31;
        cp16(ab + ((mti * 2 + k8l) * 32 + cb) * 16,
             g_xc + (size_t)((mt0 + mti) * 128 + kt16 * 2 + k8l) * 128 + cb * 4);
    }
#pragma unroll
    for (int u = 0; u < 2; u++) {                  // B: 512 chunks
        int c = tid + u * 256;
        int nt8l = c >> 5, cb = c & 31;
        cp16(bb + (nt8l * 32 + cb) * 16,
             g_wc + (size_t)((n8b + nt8l) * 64 + kt16) * 128 + cb * 4);
    }
}

__global__ __launch_bounds__(256) void kqv_gemm_mma() {
    extern __shared__ __align__(16) uint8_t smem_raw[];
    uint32_t sb = smem_u32(smem_raw);
    const int tid = threadIdx.x;
    const int warp = tid >> 5, lane = tid & 31;
    const int lr = lane >> 2, lc = lane & 3;
    const int wm = warp >> 1, wn = warp & 1;
    const int m0 = blockIdx.y * 128;
    const int n0 = blockIdx.x * 128;
    const int mt0 = blockIdx.y * 8;
    const int n8b = blockIdx.x * 16;

    float c[2][8][4];
#pragma unroll
    for (int i = 0; i < 2; i++)
#pragma unroll
        for (int j = 0; j < 8; j++)
#pragma unroll
            for (int t = 0; t < 4; t++) c[i][j][t] = 0.f;

#pragma unroll
    for (int s = 0; s < GNSTAGES - 1; s++) {
        g_load_stage(sb, s, s, tid, mt0, n8b);
        cp_commit();
    }
    cp_wait2();
    __syncthreads();

    for (int kt = 0; kt < 64; kt++) {
        int st = kt & (GNSTAGES - 1);
        const float* As = (const float*)(smem_raw + st * (GSTAGE_F * 4));
        const float* Bs = As + 2048;
        uint32_t a[2][2][4], b[8][4];
#pragma unroll
        for (int i = 0; i < 2; i++)
#pragma unroll
            for (int k8 = 0; k8 < 2; k8++) {
                const uint4 v = *(const uint4*)&As[((wm * 2 + i) * 2 + k8) * 128 + lane * 4];
                a[i][k8][0] = v.x; a[i][k8][1] = v.y; a[i][k8][2] = v.z; a[i][k8][3] = v.w;
            }
#pragma unroll
        for (int j = 0; j < 8; j++) {
            const uint4 v = *(const uint4*)&Bs[(wn * 8 + j) * 128 + lane * 4];
            b[j][0] = v.x; b[j][1] = v.y; b[j][2] = v.z; b[j][3] = v.w;
        }
#pragma unroll
        for (int k8 = 0; k8 < 2; k8++)
#pragma unroll
            for (int i = 0; i < 2; i++)
#pragma unroll
                for (int j = 0; j < 8; j++)
                    mma1688(c[i][j], a[i][k8], &b[j][k8 * 2]);
        __syncthreads();
        int nk = kt + GNSTAGES - 1;
        if (nk < 64) g_load_stage(sb, nk & (GNSTAGES - 1), nk, tid, mt0, n8b);
        cp_commit();
        cp_wait2();
        __syncthreads();
    }

    // ---- epilogue: scatter into frag-major g_q2/g_k2/g_v2 ----
    const int gc0 = n0 + wn * 64;       // 64-aligned => chunk/head fixed per warp
    const int chunk = gc0 >> 10;        // 0:k 1:q 2:v
    const int h = (gc0 & 1023) >> 6;
    const int mbase = m0 + wm * 32;

#pragma unroll
    for (int i = 0; i < 2; i++) {
#pragma unroll
        for (int j = 0; j < 8; j++) {
            float v0 = tf32_rna(c[i][j][0]), v1 = tf32_rna(c[i][j][1]);
            float v2 = tf32_rna(c[i][j][2]), v3 = tf32_rna(c[i][j][3]);
            int d = j * 8 + 2 * lc;              // cols d, d+1
            int r = mbase + i * 16 + lr;         // rows r, r+8
            if (chunk == 1) {                    // Q : a-frag
                int base = ((h * 256 + (r >> 4)) * 8 + j) * 128;
                int lp = lr * 4 + (d & 3);
                int k4 = (lc >> 1) & 1;
                *(float2*)&g_q2[base + lp * 4 + 2 * k4] = make_float2(v0, v2);
                *(float2*)&g_q2[base + (lp + 1) * 4 + 2 * k4] = make_float2(v1, v3);
            } else if (chunk == 0) {             // K : b-frag over d
                int d16 = j >> 1;
                int s = (j & 1) * 2 + (lc >> 1);
                int lp = lr * 4 + (d & 3);
                int ba = ((h * 512 + (r >> 3)) * 4 + d16) * 128;
                int bb = ((h * 512 + ((r + 8) >> 3)) * 4 + d16) * 128;
                g_k2[ba + lp * 4 + s] = v0;
                g_k2[ba + (lp + 1) * 4 + s] = v1;
                g_k2[bb + lp * 4 + s] = v2;
                g_k2[bb + (lp + 1) * 4 + s] = v3;
            } else {                             // V : b-frag transposed (k=keys)
#pragma unroll
                for (int rb = 0; rb < 2; rb++) {
                    int m = r + rb * 8;
                    float va = rb ? v2 : v0, vb = rb ? v3 : v1;
                    int base = (((h * 64 + (m >> 6)) * 8 + j) * 4 + ((m >> 4) & 3)) * 128;
                    int s = ((m >> 3) & 1) * 2 + ((m >> 2) & 1);
                    g_v2[base + ((d & 7) * 4 + (m & 3)) * 4 + s] = va;
                    g_v2[base + (((d + 1) & 7) * 4 + (m & 3)) * 4 + s] = vb;
                }
            }
        }
    }
}

// ---------------------------------------------------------------------------
// Tensor-core flash attention, frag-major. Block = 128 queries x 1 head.
// smem: KV stages 2 x 8192 floats (K 4096 + V 4096), P 8 warps x 1024 floats.
// ---------------------------------------------------------------------------
#define KV_OFF(s) ((s) * 8192)
#define P_OFF 16384
#define ATTN_SMEM ((16384 + 8192) * 4)
#define SCL 0.03125f

__device__ __forceinline__ void a_load_kv(uint32_t sb, int s, int kt, int tid,
                                          const float* __restrict__ kb,
                                          const float* __restrict__ vb) {
    uint32_t kd = sb + KV_OFF(s) * 4;
    uint32_t vd = kd + 4096 * 4;
    const float* kg = kb + (size_t)kt * 4096;
    const float* vg = vb + (size_t)kt * 4096;
#pragma unroll
    for (int u = 0; u < 4; u++) {
        int c = tid + u * 256;
        cp16(kd + c * 16, kg + c * 4);
        cp16(vd + c * 16, vg + c * 4);
    }
}

__global__ __launch_bounds__(256, 1) void attn_tc(float* __restrict__ out) {
    extern __shared__ __align__(16) uint8_t smem_raw[];
    float* sm = (float*)smem_raw;
    uint32_t sb = smem_u32(smem_raw);

    const int tid = threadIdx.x;
    const int w = tid >> 5, lane = tid & 31;
    const int lr = lane >> 2, lc = lane & 3;
    const int qt = blockIdx.x;
    const int h = blockIdx.y;
    const int q0 = qt * 128;

    const float slope = exp2f(-0.5f * (float)(h + 1));
    const float* __restrict__ kbh = g_k2 + (size_t)h * S * HD;
    const float* __restrict__ vbh = g_v2 + (size_t)h * S * HD;

    const int kt0 = (qt >= 4) ? (2 * qt - 8) : 0;
    const int kt1 = 2 * qt + 1;

    a_load_kv(sb, 0, kt0, tid, kbh, vbh);
    cp_commit();

    // Q fragments straight from gmem (coalesced LDG.128)
    uint32_t qa[8][4];
    {
        const float* qb = g_q2 + (size_t)((h * 256 + qt * 8 + w) * 8) * 128;
#pragma unroll
        for (int k8 = 0; k8 < 8; k8++) {
            uint4 v = *(const uint4*)&qb[k8 * 128 + lane * 4];
            qa[k8][0] = v.x; qa[k8][1] = v.y; qa[k8][2] = v.z; qa[k8][3] = v.w;
        }
    }

    float o[8][4];
    float m0r = -1e30f, m1r = -1e30f, l0 = 0.f, l1 = 0.f;
#pragma unroll
    for (int nt = 0; nt < 8; nt++)
#pragma unroll
        for (int t = 0; t < 4; t++) o[nt][t] = 0.f;

    const int i0 = q0 + w * 16 + lr;
    const int i1 = i0 + 8;
    float* Pw = sm + P_OFF + w * 1024;
    const float s8 = slope * 8.f;

    for (int kt = kt0; kt <= kt1; kt++) {
        int st = (kt - kt0) & 1;
        if (kt < kt1) {
            a_load_kv(sb, st ^ 1, kt + 1, tid, kbh, vbh);
            cp_commit();
            cp_wait1();
        } else {
            cp_wait0();
        }
        __syncthreads();

        const float* Ks = sm + KV_OFF(st);
        const float* Vs = Ks + 4096;
        const int kb = kt * 64;

        // ---- S = Q K^T ----
        float sc[8][4];
#pragma unroll
        for (int nt = 0; nt < 8; nt++) {
#pragma unroll
            for (int t = 0; t < 4; t++) sc[nt][t] = 0.f;
#pragma unroll
            for (int k16 = 0; k16 < 4; k16++) {
                uint4 v = *(const uint4*)&Ks[(nt * 4 + k16) * 128 + lane * 4];
                uint32_t b[4] = {v.x, v.y, v.z, v.w};
                mma1688(sc[nt], qa[k16 * 2], &b[0]);
                mma1688(sc[nt], qa[k16 * 2 + 1], &b[2]);
            }
        }

        // ---- bias/mask + online softmax ----
        const bool full = (kt <= 2 * qt - 1) && (kt >= 2 * qt - 6);
        float mx0 = -3e38f, mx1 = -3e38f;
        if (full) {
            float bias = slope * (float)(kb + 2 * lc - i0);
#pragma unroll
            for (int nt = 0; nt < 8; nt++) {
                sc[nt][0] = fmaf(sc[nt][0], SCL, bias);
                sc[nt][1] = fmaf(sc[nt][1], SCL, bias + slope);
                sc[nt][2] = fmaf(sc[nt][2], SCL, bias - s8);
                sc[nt][3] = fmaf(sc[nt][3], SCL, bias - s8 + slope);
                mx0 = fmaxf(mx0, fmaxf(sc[nt][0], sc[nt][1]));
                mx1 = fmaxf(mx1, fmaxf(sc[nt][2], sc[nt][3]));
                bias += s8;
            }
        } else {
#pragma unroll
            for (int nt = 0; nt < 8; nt++) {
                int j0 = kb + nt * 8 + 2 * lc;
                int d00 = i0 - j0;
                sc[nt][0] = (d00 >= 0 && d00 <= WIN)
                                ? fmaf(sc[nt][0], SCL, slope * (float)(-d00)) : -3e38f;
                int d01 = d00 - 1;
                sc[nt][1] = (d01 >= 0 && d01 <= WIN)
                                ? fmaf(sc[nt][1], SCL, slope * (float)(-d01)) : -3e38f;
                int d10 = i1 - j0;
                sc[nt][2] = (d10 >= 0 && d10 <= WIN)
                                ? fmaf(sc[nt][2], SCL, slope * (float)(-d10)) : -3e38f;
                int d11 = d10 - 1;
                sc[nt][3] = (d11 >= 0 && d11 <= WIN)
                                ? fmaf(sc[nt][3], SCL, slope * (float)(-d11)) : -3e38f;
                mx0 = fmaxf(mx0, fmaxf(sc[nt][0], sc[nt][1]));
                mx1 = fmaxf(mx1, fmaxf(sc[nt][2], sc[nt][3]));
            }
        }
        mx0 = fmaxf(mx0, __shfl_xor_sync(0xffffffffu, mx0, 1));
        mx0 = fmaxf(mx0, __shfl_xor_sync(0xffffffffu, mx0, 2));
        mx1 = fmaxf(mx1, __shfl_xor_sync(0xffffffffu, mx1, 1));
        mx1 = fmaxf(mx1, __shfl_xor_sync(0xffffffffu, mx1, 2));

        float mn0 = fmaxf(m0r, mx0), mn1 = fmaxf(m1r, mx1);
        float al0 = __expf(m0r - mn0), al1 = __expf(m1r - mn1);
        m0r = mn0; m1r = mn1;

        // ---- exp, row-sum, store P in a-frag layout ----
        const int lp = lr * 4 + ((2 * lc) & 3);
        const int k4b = 2 * ((lc >> 1) & 1);
        float rs0 = 0.f, rs1 = 0.f;
#pragma unroll
        for (int nt = 0; nt < 8; nt++) {
            float p00 = tf32_rna(__expf(sc[nt][0] - mn0));
            float p01 = tf32_rna(__expf(sc[nt][1] - mn0));
            float p10 = tf32_rna(__expf(sc[nt][2] - mn1));
            float p11 = tf32_rna(__expf(sc[nt][3] - mn1));
            rs0 += p00 + p01;
            rs1 += p10 + p11;
            *(float2*)&Pw[nt * 128 + lp * 4 + k4b] = make_float2(p00, p10);
            *(float2*)&Pw[nt * 128 + (lp + 1) * 4 + k4b] = make_float2(p01, p11);
        }
        rs0 += __shfl_xor_sync(0xffffffffu, rs0, 1);
        rs0 += __shfl_xor_sync(0xffffffffu, rs0, 2);
        rs1 += __shfl_xor_sync(0xffffffffu, rs1, 1);
        rs1 += __shfl_xor_sync(0xffffffffu, rs1, 2);
        l0 = l0 * al0 + rs0;
        l1 = l1 * al1 + rs1;
#pragma unroll
        for (int nt = 0; nt < 8; nt++) {
            o[nt][0] *= al0; o[nt][1] *= al0;
            o[nt][2] *= al1; o[nt][3] *= al1;
        }
        __syncwarp();

        // ---- P a-frags ----
        uint32_t pa[8][4];
#pragma unroll
        for (int k8 = 0; k8 < 8; k8++) {
            uint4 v = *(const uint4*)&Pw[k8 * 128 + lane * 4];
            pa[k8][0] = v.x; pa[k8][1] = v.y; pa[k8][2] = v.z; pa[k8][3] = v.w;
        }

        // ---- O += P V ----
#pragma unroll
        for (int nt = 0; nt < 8; nt++) {
#pragma unroll
            for (int k16 = 0; k16 < 4; k16++) {
                uint4 v = *(const uint4*)&Vs[(nt * 4 + k16) * 128 + lane * 4];
                uint32_t b[4] = {v.x, v.y, v.z, v.w};
                mma1688(o[nt], pa[k16 * 2], &b[0]);
                mma1688(o[nt], pa[k16 * 2 + 1], &b[2]);
            }
        }
        __syncthreads();
    }

    // ---- normalize + write ----
    float inv0 = 1.f / l0, inv1 = 1.f / l1;
    float* o0 = out + (size_t)i0 * DM + h * HD;
    float* o1 = out + (size_t)i1 * DM + h * HD;
#pragma unroll
    for (int nt = 0; nt < 8; nt++) {
        *(float2*)&o0[nt * 8 + 2 * lc] = make_float2(o[nt][0] * inv0, o[nt][1] * inv0);
        *(float2*)&o1[nt * 8 + 2 * lc] = make_float2(o[nt][2] * inv1, o[nt][3] * inv1);
    }
}

// ---------------------------------------------------------------------------
extern "C" void kernel_launch(void* const* d_in, const int* in_sizes, int n_in,
                              void* d_out, int out_size) {
    const float* x = (const float*)d_in[0];
    const float* w = (const float*)d_in[1];
    if (n_in >= 2 && in_sizes[0] == DM * NK && in_sizes[1] == S * DM) {
        const float* t = x; x = w; w = t;
    }
    float* out = (float*)d_out;

    static int attr_set = 0;
    if (!attr_set) {
        cudaFuncSetAttribute(kqv_gemm_mma, cudaFuncAttributeMaxDynamicSharedMemorySize,
                             GEMM_SMEM);
        cudaFuncSetAttribute(attn_tc, cudaFuncAttributeMaxDynamicSharedMemorySize,
                             ATTN_SMEM);
        attr_set = 1;
    }

    prep_x<<<4096, 256>>>(x);
    prep_w<<<3072, 256>>>(w);

    dim3 ggrid(NK / 128, S / 128);
    kqv_gemm_mma<<<ggrid, 256, GEMM_SMEM>>>();

    dim3 agrid(S / 128, H);
    attn_tc<<<agrid, 256, ATTN_SMEM>>>(out);
}